// round 3
// baseline (speedup 1.0000x reference)
#include <cuda_runtime.h>
#include <cuda_bf16.h>

// ---------------------------------------------------------------------------
// Fused LEMURS actor:
//   h1 = silu(x @ W_in^T + b_in)                      (B,128)
//   attn1: q,k,v = silu(h1 @ A^T + B); per-element softmax attention  (B,128)
//   h2 = silu(attn1 @ W_h^T + b_h)                    (B,64)
//   attn2: same with 64-dim                           (B,64)
//   y = silu(h2a @ W_out^T + b_out)                   (B,25)
//   scalar quad-form reduction -> (B,1)
// ---------------------------------------------------------------------------

#define RPB 16          // rows per block
#define NTHREADS 256

// Transposed weights (column-major so per-j weight loads are coalesced)
__device__ float g_WinT[12 * 128];
__device__ float g_AqT1[128 * 128];
__device__ float g_AkT1[128 * 128];
__device__ float g_AvT1[128 * 128];
__device__ float g_WhT[128 * 64];
__device__ float g_AqT2[64 * 64];
__device__ float g_AkT2[64 * 64];
__device__ float g_AvT2[64 * 64];

__device__ __forceinline__ float ex2f(float x) {
    float y;
    asm("ex2.approx.ftz.f32 %0, %1;" : "=f"(y) : "f"(x));
    return y;
}

__device__ __forceinline__ float siluf(float v) {
    // v * sigmoid(v); __expf + approx divide: ~2^-21 rel err, fine vs 1e-3 tol
    return __fdividef(v, 1.0f + __expf(-v));
}

__global__ void prep_weights(const float* __restrict__ Win,
                             const float* __restrict__ Aq1,
                             const float* __restrict__ Ak1,
                             const float* __restrict__ Av1,
                             const float* __restrict__ Wh,
                             const float* __restrict__ Aq2,
                             const float* __restrict__ Ak2,
                             const float* __restrict__ Av2) {
    int t = blockIdx.x * blockDim.x + threadIdx.x;
    int stride = gridDim.x * blockDim.x;
    // W_in: (128,12) -> WinT[j*128+i]
    for (int idx = t; idx < 128 * 12; idx += stride) {
        int i = idx / 12, j = idx - i * 12;
        g_WinT[j * 128 + i] = Win[idx];
    }
    // A*1: (128,128) -> [j*128+i]
    for (int idx = t; idx < 128 * 128; idx += stride) {
        int i = idx >> 7, j = idx & 127;
        g_AqT1[j * 128 + i] = Aq1[idx];
        g_AkT1[j * 128 + i] = Ak1[idx];
        g_AvT1[j * 128 + i] = Av1[idx];
    }
    // W_h: (64,128) -> WhT[j*64+i]
    for (int idx = t; idx < 64 * 128; idx += stride) {
        int i = idx >> 7, j = idx & 127;
        g_WhT[j * 64 + i] = Wh[idx];
    }
    // A*2: (64,64) -> [j*64+i]
    for (int idx = t; idx < 64 * 64; idx += stride) {
        int i = idx >> 6, j = idx & 63;
        g_AqT2[j * 64 + i] = Aq2[idx];
        g_AkT2[j * 64 + i] = Ak2[idx];
        g_AvT2[j * 64 + i] = Av2[idx];
    }
}

__global__ __launch_bounds__(NTHREADS)
void lemurs_fused(const float* __restrict__ x,
                  const float* __restrict__ b_in,
                  const float* __restrict__ Bq1, const float* __restrict__ Bk1,
                  const float* __restrict__ Bv1,
                  const float* __restrict__ b_h,
                  const float* __restrict__ Bq2, const float* __restrict__ Bk2,
                  const float* __restrict__ Bv2,
                  const float* __restrict__ Wout,
                  const float* __restrict__ b_out,
                  float* __restrict__ out) {
    __shared__ float sx[RPB * 12];          // staged input
    __shared__ float sh[RPB * 128];         // h1 -> attn1out -> attn2out/y
    __shared__ float sq[RPB * 128];         // q1 (prescaled) -> h2 | q2
    __shared__ float skv[RPB * 128 * 2];    // interleaved (k,v)

    const int t = threadIdx.x;
    const int row0 = blockIdx.x * RPB;
    const float LOG2E = 1.4426950408889634f;

    // stage x
    for (int idx = t; idx < RPB * 12; idx += NTHREADS)
        sx[idx] = x[row0 * 12 + idx];
    __syncthreads();

    const int i = t & 127;   // feature index (128-wide phases)
    const int g = t >> 7;    // 0/1: which 8-row half
    const int i2 = t & 63;   // feature index (64-wide phases)
    const int g4 = t >> 6;   // 0..3: which 4-row quarter

    // ---- phase 1: h1 = silu(x @ W_in^T + b_in) ----
    {
        float acc[8];
        float bb = b_in[i];
#pragma unroll
        for (int r = 0; r < 8; r++) acc[r] = bb;
#pragma unroll
        for (int j = 0; j < 12; j++) {
            float w = g_WinT[j * 128 + i];
#pragma unroll
            for (int r = 0; r < 8; r++)
                acc[r] += w * sx[(g * 8 + r) * 12 + j];
        }
#pragma unroll
        for (int r = 0; r < 8; r++)
            sh[(g * 8 + r) * 128 + i] = siluf(acc[r]);
    }
    __syncthreads();

    // ---- phase 2: q1,k1,v1 GEMMs (128x128 each) ----
    {
        float aq[8], ak[8], av[8];
        float bq = Bq1[i], bk = Bk1[i], bv = Bv1[i];
#pragma unroll
        for (int r = 0; r < 8; r++) { aq[r] = bq; ak[r] = bk; av[r] = bv; }
#pragma unroll 4
        for (int j = 0; j < 128; j++) {
            float wq = g_AqT1[j * 128 + i];
            float wk = g_AkT1[j * 128 + i];
            float wv = g_AvT1[j * 128 + i];
#pragma unroll
            for (int r = 0; r < 8; r++) {
                float hv = sh[(g * 8 + r) * 128 + j];
                aq[r] += wq * hv;
                ak[r] += wk * hv;
                av[r] += wv * hv;
            }
        }
#pragma unroll
        for (int r = 0; r < 8; r++) {
            int row = g * 8 + r;
            sq[row * 128 + i] = siluf(aq[r]) * LOG2E;     // prescale for ex2
            skv[(row * 128 + i) * 2 + 0] = siluf(ak[r]);
            skv[(row * 128 + i) * 2 + 1] = siluf(av[r]);
        }
    }
    __syncthreads();

    // ---- phase 3: attention 1 (128x128 pairs per row) ----
    {
#pragma unroll
        for (int r = 0; r < 8; r++) {
            int row = g * 8 + r;
            float qv = sq[row * 128 + i];
            float num = 0.f, den = 0.f;
            const float2* kv = (const float2*)&skv[row * 256];
#pragma unroll 16
            for (int j = 0; j < 128; j++) {
                float2 p = kv[j];
                float e = ex2f(qv * p.x);
                num += e * p.y;
                den += e;
            }
            sh[row * 128 + i] = siluf(__fdividef(num, den));
        }
    }
    __syncthreads();

    // ---- phase 4: h2 = silu(attn1 @ W_h^T + b_h)  (64 out, 128-dot) ----
    {
        float acc[4];
        float bb = b_h[i2];
#pragma unroll
        for (int r = 0; r < 4; r++) acc[r] = bb;
#pragma unroll 4
        for (int j = 0; j < 128; j++) {
            float w = g_WhT[j * 64 + i2];
#pragma unroll
            for (int r = 0; r < 4; r++)
                acc[r] += w * sh[(g4 * 4 + r) * 128 + j];
        }
#pragma unroll
        for (int r = 0; r < 4; r++)
            sq[(g4 * 4 + r) * 64 + i2] = siluf(acc[r]);   // h2 in sq[0..1024)
    }
    __syncthreads();

    // ---- phase 5: q2,k2,v2 GEMMs (64x64 each) ----
    {
        float aq[4], ak[4], av[4];
        float bq = Bq2[i2], bk = Bk2[i2], bv = Bv2[i2];
#pragma unroll
        for (int r = 0; r < 4; r++) { aq[r] = bq; ak[r] = bk; av[r] = bv; }
#pragma unroll 4
        for (int j = 0; j < 64; j++) {
            float wq = g_AqT2[j * 64 + i2];
            float wk = g_AkT2[j * 64 + i2];
            float wv = g_AvT2[j * 64 + i2];
#pragma unroll
            for (int r = 0; r < 4; r++) {
                float hv = sq[(g4 * 4 + r) * 64 + j];
                aq[r] += wq * hv;
                ak[r] += wk * hv;
                av[r] += wv * hv;
            }
        }
#pragma unroll
        for (int r = 0; r < 4; r++) {
            int row = g4 * 4 + r;
            sq[1024 + row * 64 + i2] = siluf(aq[r]) * LOG2E;
            skv[(row * 64 + i2) * 2 + 0] = siluf(ak[r]);
            skv[(row * 64 + i2) * 2 + 1] = siluf(av[r]);
        }
    }
    __syncthreads();

    // ---- phase 6: attention 2 (64x64 pairs per row) ----
    {
#pragma unroll
        for (int r = 0; r < 4; r++) {
            int row = g4 * 4 + r;
            float qv = sq[1024 + row * 64 + i2];
            float num = 0.f, den = 0.f;
            const float2* kv = (const float2*)&skv[row * 128];
#pragma unroll 16
            for (int j = 0; j < 64; j++) {
                float2 p = kv[j];
                float e = ex2f(qv * p.x);
                num += e * p.y;
                den += e;
            }
            sh[row * 64 + i2] = siluf(__fdividef(num, den));
        }
    }
    __syncthreads();

    // ---- phase 7: y = silu(h2a @ W_out^T + b_out) (25 out, 64-dot) ----
    for (int idx = t; idx < RPB * 25; idx += NTHREADS) {
        int r = idx / 25;
        int o = idx - r * 25;
        float acc = b_out[o];
        const float* wrow = &Wout[o * 64];
        const float* arow = &sh[r * 64];
#pragma unroll 8
        for (int j = 0; j < 64; j++)
            acc += wrow[j] * arow[j];
        sh[1024 + idx] = siluf(acc);
    }
    __syncthreads();

    // ---- phase 8: quadratic-form reduction ----
    if (t < RPB) {
        const float* y = &sh[1024 + t * 25];
        float M11 = 0.f, M12 = 0.f, M21 = 0.f, M22 = 0.f, Mpp = 0.f;
#pragma unroll
        for (int j = 0; j < 5; j++) {
            M11 += y[j] * y[j];
            M12 += y[5 + j] * y[5 + j];
            M21 += y[10 + j] * y[10 + j];
            M22 += y[15 + j] * y[15 + j];
            Mpp += y[20 + j] * y[20 + j];
        }
        float q0 = y[0], q1 = y[1], q2 = y[2], q3 = y[3];
        float quad = M11 * (q0 * q0 + q1 * q1)
                   + (M12 + M21) * (q0 * q2 + q1 * q3)
                   + M22 * (q2 * q2 + q3 * q3);
        out[row0 + t] = quad + Mpp;
    }
}

extern "C" void kernel_launch(void* const* d_in, const int* in_sizes, int n_in,
                              void* d_out, int out_size) {
    const float* x     = (const float*)d_in[0];
    // d_in[1] = na (unused)
    const float* W_in  = (const float*)d_in[2];
    const float* b_in  = (const float*)d_in[3];
    const float* Aq4   = (const float*)d_in[4];
    const float* Bq4   = (const float*)d_in[5];
    const float* Ak4   = (const float*)d_in[6];
    const float* Bk4   = (const float*)d_in[7];
    const float* Av4   = (const float*)d_in[8];
    const float* Bv4   = (const float*)d_in[9];
    const float* W_h   = (const float*)d_in[10];
    const float* b_h   = (const float*)d_in[11];
    const float* Aq7   = (const float*)d_in[12];
    const float* Bq7   = (const float*)d_in[13];
    const float* Ak7   = (const float*)d_in[14];
    const float* Bk7   = (const float*)d_in[15];
    const float* Av7   = (const float*)d_in[16];
    const float* Bv7   = (const float*)d_in[17];
    const float* W_out = (const float*)d_in[18];
    const float* b_out = (const float*)d_in[19];

    int nrows = in_sizes[0] / 12;

    prep_weights<<<64, 256>>>(W_in, Aq4, Ak4, Av4, W_h, Aq7, Ak7, Av7);
    lemurs_fused<<<nrows / RPB, NTHREADS>>>(x, b_in, Bq4, Bk4, Bv4,
                                            b_h, Bq7, Bk7, Bv7,
                                            W_out, b_out, (float*)d_out);
}

// round 6
// speedup vs baseline: 1.4699x; 1.4699x over previous
#include <cuda_runtime.h>
#include <cuda_bf16.h>

// ---------------------------------------------------------------------------
// Fused LEMURS actor, round 3:
//  - f32x2 packed FFMA in all GEMM phases (halves FMA instruction count)
//  - feature-major (stride-20) activation layout -> LDS.128 row loads that
//    reinterpret directly as f32x2 operand pairs
//  - q kept in registers between qkv-GEMM and attention (same thread mapping)
//  - __launch_bounds__(256,4): 64 regs -> 4 blocks/SM (50% occupancy)
// ---------------------------------------------------------------------------

#define RPB 16
#define NTHREADS 256

typedef unsigned long long u64;

// Transposed weights (column-major: per-j loads are one 128B line per warp)
__device__ float g_WinT[12 * 128];
__device__ float g_AqT1[128 * 128];
__device__ float g_AkT1[128 * 128];
__device__ float g_AvT1[128 * 128];
__device__ float g_WhT[128 * 64];
__device__ float g_AqT2[64 * 64];
__device__ float g_AkT2[64 * 64];
__device__ float g_AvT2[64 * 64];

__device__ __forceinline__ u64 pack2(float a, float b) {
    u64 r;
    asm("mov.b64 %0, {%1, %2};" : "=l"(r) : "f"(a), "f"(b));
    return r;
}
__device__ __forceinline__ void ffma2(u64& d, u64 a, u64 b) {
    asm("fma.rn.f32x2 %0, %1, %2, %0;" : "+l"(d) : "l"(a), "l"(b));
}
__device__ __forceinline__ float2 unpack2(u64 v) {
    float2 f;
    asm("mov.b64 {%0, %1}, %2;" : "=f"(f.x), "=f"(f.y) : "l"(v));
    return f;
}
__device__ __forceinline__ float ex2f(float x) {
    float y;
    asm("ex2.approx.ftz.f32 %0, %1;" : "=f"(y) : "f"(x));
    return y;
}
__device__ __forceinline__ float siluf(float v) {
    return __fdividef(v, 1.0f + __expf(-v));
}

__global__ void prep_weights(const float* __restrict__ Win,
                             const float* __restrict__ Aq1,
                             const float* __restrict__ Ak1,
                             const float* __restrict__ Av1,
                             const float* __restrict__ Wh,
                             const float* __restrict__ Aq2,
                             const float* __restrict__ Ak2,
                             const float* __restrict__ Av2) {
    int t = blockIdx.x * blockDim.x + threadIdx.x;
    int stride = gridDim.x * blockDim.x;
    for (int idx = t; idx < 128 * 12; idx += stride) {
        int i = idx / 12, j = idx - i * 12;
        g_WinT[j * 128 + i] = Win[idx];
    }
    for (int idx = t; idx < 128 * 128; idx += stride) {
        int i = idx >> 7, j = idx & 127;
        g_AqT1[j * 128 + i] = Aq1[idx];
        g_AkT1[j * 128 + i] = Ak1[idx];
        g_AvT1[j * 128 + i] = Av1[idx];
    }
    for (int idx = t; idx < 64 * 128; idx += stride) {
        int i = idx >> 7, j = idx & 127;
        g_WhT[j * 64 + i] = Wh[idx];
    }
    for (int idx = t; idx < 64 * 64; idx += stride) {
        int i = idx >> 6, j = idx & 63;
        g_AqT2[j * 64 + i] = Aq2[idx];
        g_AkT2[j * 64 + i] = Ak2[idx];
        g_AvT2[j * 64 + i] = Av2[idx];
    }
}

__global__ __launch_bounds__(NTHREADS, 4)
void lemurs_fused(const float* __restrict__ x,
                  const float* __restrict__ b_in,
                  const float* __restrict__ Bq1, const float* __restrict__ Bk1,
                  const float* __restrict__ Bv1,
                  const float* __restrict__ b_h,
                  const float* __restrict__ Bq2, const float* __restrict__ Bk2,
                  const float* __restrict__ Bv2,
                  const float* __restrict__ Wout,
                  const float* __restrict__ b_out,
                  float* __restrict__ out) {
    // feature-major activation tiles, stride 20 (conflict-free for 8-lane
    // STS.128 phases: 20*i mod 32 hits all distinct banks)
    __shared__ __align__(16) float sx[RPB * 12];       //  768 B
    __shared__ __align__(16) float shT[128 * 20];      // 10 KB  h1 -> attn1out
    __shared__ __align__(16) float skv[RPB * 128 * 2]; // 16 KB  (k,v) attn1
    __shared__ __align__(16) float sh2T[64 * 20];      //  5 KB  h2
    __shared__ __align__(16) float skv2[RPB * 64 * 2]; //  8 KB  (k,v) attn2
    __shared__ __align__(16) float sAt2[RPB * 64];     //  4 KB  attn2 out
    __shared__ float sy[RPB * 25];                     // 1.6 KB y

    const int t = threadIdx.x;
    const int row0 = blockIdx.x * RPB;
    const float LOG2E = 1.4426950408889634f;

    if (t < RPB * 12) sx[t] = x[row0 * 12 + t];
    __syncthreads();

    const int i  = t & 127;  // feature (128-wide phases)
    const int g  = t >> 7;   // 0/1: 8-row half
    const int i2 = t & 63;   // feature (64-wide phases)
    const int g4 = t >> 6;   // 0..3: 4-row quarter

    // ---- phase 1: h1 = silu(x @ W_in^T + b_in) -> shT[feat*20 + row] ----
    {
        float acc[8];
        float bb = b_in[i];
#pragma unroll
        for (int r = 0; r < 8; r++) acc[r] = bb;
#pragma unroll
        for (int j = 0; j < 12; j++) {
            float w = g_WinT[j * 128 + i];
#pragma unroll
            for (int r = 0; r < 8; r++)
                acc[r] += w * sx[(g * 8 + r) * 12 + j];
        }
        float4 o0 = make_float4(siluf(acc[0]), siluf(acc[1]),
                                siluf(acc[2]), siluf(acc[3]));
        float4 o1 = make_float4(siluf(acc[4]), siluf(acc[5]),
                                siluf(acc[6]), siluf(acc[7]));
        *(float4*)&shT[i * 20 + g * 8]     = o0;
        *(float4*)&shT[i * 20 + g * 8 + 4] = o1;
    }
    __syncthreads();

    // ---- phase 2: q1,k1,v1 = silu(h1 @ A^T + B), f32x2 packed ----
    float q[8];  // prescaled q lives in registers through phase 3
    {
        u64 aq[4], ak[4], av[4];
        float bq = Bq1[i], bk = Bk1[i], bv = Bv1[i];
        u64 bq2 = pack2(bq, bq), bk2 = pack2(bk, bk), bv2 = pack2(bv, bv);
#pragma unroll
        for (int p = 0; p < 4; p++) { aq[p] = bq2; ak[p] = bk2; av[p] = bv2; }
#pragma unroll 4
        for (int j = 0; j < 128; j++) {
            float wq = g_AqT1[j * 128 + i];
            float wk = g_AkT1[j * 128 + i];
            float wv = g_AvT1[j * 128 + i];
            u64 wq2 = pack2(wq, wq), wk2 = pack2(wk, wk), wv2 = pack2(wv, wv);
            ulonglong2 ha = *(const ulonglong2*)&shT[j * 20 + g * 8];
            ulonglong2 hb = *(const ulonglong2*)&shT[j * 20 + g * 8 + 4];
            ffma2(aq[0], wq2, ha.x); ffma2(aq[1], wq2, ha.y);
            ffma2(aq[2], wq2, hb.x); ffma2(aq[3], wq2, hb.y);
            ffma2(ak[0], wk2, ha.x); ffma2(ak[1], wk2, ha.y);
            ffma2(ak[2], wk2, hb.x); ffma2(ak[3], wk2, hb.y);
            ffma2(av[0], wv2, ha.x); ffma2(av[1], wv2, ha.y);
            ffma2(av[2], wv2, hb.x); ffma2(av[3], wv2, hb.y);
        }
        float2* kvp = (float2*)skv;
#pragma unroll
        for (int p = 0; p < 4; p++) {
            float2 fq = unpack2(aq[p]);
            float2 fk = unpack2(ak[p]);
            float2 fv = unpack2(av[p]);
            int row = g * 8 + 2 * p;
            q[2 * p]     = siluf(fq.x) * LOG2E;
            q[2 * p + 1] = siluf(fq.y) * LOG2E;
            kvp[row * 128 + i]       = make_float2(siluf(fk.x), siluf(fv.x));
            kvp[(row + 1) * 128 + i] = make_float2(siluf(fk.y), siluf(fv.y));
        }
    }
    __syncthreads();

    // ---- phase 3: attention 1 (q in regs, kv broadcast from smem) ----
    {
#pragma unroll
        for (int r = 0; r < 8; r++) {
            int row = g * 8 + r;
            float qv = q[r];
            const float2* kv = (const float2*)&skv[row * 256];
            float num = 0.f, den = 0.f;
#pragma unroll 8
            for (int j = 0; j < 128; j++) {
                float2 p = kv[j];
                float e = ex2f(qv * p.x);
                num += e * p.y;
                den += e;
            }
            shT[i * 20 + row] = siluf(__fdividef(num, den));
        }
    }
    __syncthreads();

    // ---- phase 4: h2 = silu(attn1 @ W_h^T + b_h) -> sh2T[feat*20 + row] ----
    {
        u64 a2[2];
        float bb = b_h[i2];
        a2[0] = a2[1] = pack2(bb, bb);
#pragma unroll 4
        for (int j = 0; j < 128; j++) {
            float w = g_WhT[j * 64 + i2];
            u64 w2 = pack2(w, w);
            ulonglong2 hv = *(const ulonglong2*)&shT[j * 20 + g4 * 4];
            ffma2(a2[0], w2, hv.x);
            ffma2(a2[1], w2, hv.y);
        }
        float2 f0 = unpack2(a2[0]), f1 = unpack2(a2[1]);
        float4 o = make_float4(siluf(f0.x), siluf(f0.y),
                               siluf(f1.x), siluf(f1.y));
        *(float4*)&sh2T[i2 * 20 + g4 * 4] = o;
    }
    __syncthreads();

    // ---- phase 5: q2,k2,v2 GEMMs (64x64), f32x2 packed ----
    float q2[4];
    {
        u64 aq[2], ak[2], av[2];
        float bq = Bq2[i2], bk = Bk2[i2], bv = Bv2[i2];
        aq[0] = aq[1] = pack2(bq, bq);
        ak[0] = ak[1] = pack2(bk, bk);
        av[0] = av[1] = pack2(bv, bv);
#pragma unroll 4
        for (int j = 0; j < 64; j++) {
            float wq = g_AqT2[j * 64 + i2];
            float wk = g_AkT2[j * 64 + i2];
            float wv = g_AvT2[j * 64 + i2];
            u64 wq2 = pack2(wq, wq), wk2 = pack2(wk, wk), wv2 = pack2(wv, wv);
            ulonglong2 hv = *(const ulonglong2*)&sh2T[j * 20 + g4 * 4];
            ffma2(aq[0], wq2, hv.x); ffma2(aq[1], wq2, hv.y);
            ffma2(ak[0], wk2, hv.x); ffma2(ak[1], wk2, hv.y);
            ffma2(av[0], wv2, hv.x); ffma2(av[1], wv2, hv.y);
        }
        float2* kvp = (float2*)skv2;
#pragma unroll
        for (int p = 0; p < 2; p++) {
            float2 fq = unpack2(aq[p]);
            float2 fk = unpack2(ak[p]);
            float2 fv = unpack2(av[p]);
            int row = g4 * 4 + 2 * p;
            q2[2 * p]     = siluf(fq.x) * LOG2E;
            q2[2 * p + 1] = siluf(fq.y) * LOG2E;
            kvp[row * 64 + i2]       = make_float2(siluf(fk.x), siluf(fv.x));
            kvp[(row + 1) * 64 + i2] = make_float2(siluf(fk.y), siluf(fv.y));
        }
    }
    __syncthreads();

    // ---- phase 6: attention 2 ----
    {
#pragma unroll
        for (int r = 0; r < 4; r++) {
            int row = g4 * 4 + r;
            float qv = q2[r];
            const float2* kv = (const float2*)&skv2[row * 128];
            float num = 0.f, den = 0.f;
#pragma unroll 8
            for (int j = 0; j < 64; j++) {
                float2 p = kv[j];
                float e = ex2f(qv * p.x);
                num += e * p.y;
                den += e;
            }
            sAt2[row * 64 + i2] = siluf(__fdividef(num, den));
        }
    }
    __syncthreads();

    // ---- phase 7: y = silu(attn2 @ W_out^T + b_out) ----
    for (int idx = t; idx < RPB * 25; idx += NTHREADS) {
        int r = idx / 25;
        int o = idx - r * 25;
        float acc = b_out[o];
        const float4* wrow = (const float4*)&Wout[o * 64];
        const float4* arow = (const float4*)&sAt2[r * 64];
#pragma unroll
        for (int j = 0; j < 16; j++) {
            float4 w = wrow[j];
            float4 a = arow[j];
            acc += w.x * a.x + w.y * a.y + w.z * a.z + w.w * a.w;
        }
        sy[idx] = siluf(acc);
    }
    __syncthreads();

    // ---- phase 8: quadratic-form reduction ----
    if (t < RPB) {
        const float* y = &sy[t * 25];
        float M11 = 0.f, M12 = 0.f, M21 = 0.f, M22 = 0.f, Mpp = 0.f;
#pragma unroll
        for (int j = 0; j < 5; j++) {
            M11 += y[j] * y[j];
            M12 += y[5 + j] * y[5 + j];
            M21 += y[10 + j] * y[10 + j];
            M22 += y[15 + j] * y[15 + j];
            Mpp += y[20 + j] * y[20 + j];
        }
        float q0 = y[0], q1 = y[1], qq2 = y[2], q3 = y[3];
        float quad = M11 * (q0 * q0 + q1 * q1)
                   + (M12 + M21) * (q0 * qq2 + q1 * q3)
                   + M22 * (qq2 * qq2 + q3 * q3);
        out[row0 + t] = quad + Mpp;
    }
}

extern "C" void kernel_launch(void* const* d_in, const int* in_sizes, int n_in,
                              void* d_out, int out_size) {
    const float* x     = (const float*)d_in[0];
    const float* W_in  = (const float*)d_in[2];
    const float* b_in  = (const float*)d_in[3];
    const float* Aq4   = (const float*)d_in[4];
    const float* Bq4   = (const float*)d_in[5];
    const float* Ak4   = (const float*)d_in[6];
    const float* Bk4   = (const float*)d_in[7];
    const float* Av4   = (const float*)d_in[8];
    const float* Bv4   = (const float*)d_in[9];
    const float* W_h   = (const float*)d_in[10];
    const float* b_h   = (const float*)d_in[11];
    const float* Aq7   = (const float*)d_in[12];
    const float* Bq7   = (const float*)d_in[13];
    const float* Ak7   = (const float*)d_in[14];
    const float* Bk7   = (const float*)d_in[15];
    const float* Av7   = (const float*)d_in[16];
    const float* Bv7   = (const float*)d_in[17];
    const float* W_out = (const float*)d_in[18];
    const float* b_out = (const float*)d_in[19];

    int nrows = in_sizes[0] / 12;

    prep_weights<<<64, 256>>>(W_in, Aq4, Ak4, Av4, W_h, Aq7, Ak7, Av7);
    lemurs_fused<<<nrows / RPB, NTHREADS>>>(x, b_in, Bq4, Bk4, Bv4,
                                            b_h, Bq7, Bk7, Bv7,
                                            W_out, b_out, (float*)d_out);
}